// round 17
// baseline (speedup 1.0000x reference)
#include <cuda_runtime.h>
#include <cuda_bf16.h>

// Quantumnet fused kernel. Warp-per-batch-element circuit, statevector
// (1024 f32) in registers as 16 x f32x2 packs per lane. Wire->bit map:
//   lane bits L4..L0  = wires 0,2,4,6,8 ; pack bits P3..P0 = wires 1,3,5,7 ;
//   pack slot (lo/hi) = wire 9.
// Tan-half-angle RYs, global cosine product folded into init, deferred slot
// swap for CNOT(8->9) (R12 circuit, bit-exact vs R8).
// R17: (a) SPLIT-K FRONT across all 8 warps: warp w = element-pair (w>>1),
//      K-half (w&1); halves combined in smem as pre-activation partials.
//      (b) ry_pack negative bank computed by sign-flip XOR (ALU) instead of
//      a second LDS (-24 LDS.64/warp off the MIO pipe).

#define WARPS_PER_BLOCK 8
#define THREADS (WARPS_PER_BLOCK * 32)
typedef unsigned long long u64;

__device__ __forceinline__ u64 pk2(float lo, float hi) {
    u64 r; asm("mov.b64 %0,{%1,%2};" : "=l"(r) : "f"(lo), "f"(hi)); return r;
}
__device__ __forceinline__ void upk2(u64 x, float& lo, float& hi) {
    asm("mov.b64 {%0,%1},%2;" : "=f"(lo), "=f"(hi) : "l"(x));
}
__device__ __forceinline__ u64 fma2(u64 a, u64 b, u64 c) {
    u64 d; asm("fma.rn.f32x2 %0,%1,%2,%3;" : "=l"(d) : "l"(a), "l"(b), "l"(c)); return d;
}
__device__ __forceinline__ u64 mul2(u64 a, u64 b) {
    u64 d; asm("mul.rn.f32x2 %0,%1,%2;" : "=l"(d) : "l"(a), "l"(b)); return d;
}
__device__ __forceinline__ u64 add2(u64 a, u64 b) {
    u64 d; asm("add.rn.f32x2 %0,%1,%2;" : "=l"(d) : "l"(a), "l"(b)); return d;
}
__device__ __forceinline__ u64 neg2(u64 a) {   // flip both packed f32 signs (ALU)
    return a ^ 0x8000000080000000ull;
}
__device__ __forceinline__ u64 shfl64(u64 x, int m) {
    return __shfl_xor_sync(0xffffffffu, x, m);
}
__device__ __forceinline__ float tanh_apx(float x) {
    float y; asm("tanh.approx.f32 %0,%1;" : "=f"(y) : "f"(x)); return y;
}
__device__ __forceinline__ u64 wsum2(u64 x) {
#pragma unroll
    for (int m = 16; m; m >>= 1) x = add2(x, shfl64(x, m));
    return x;
}

// ---- circuit ops (R12, proven) ----

template <int Q>
__device__ __forceinline__ void ry_lane(u64* v, u64 ts) {
#pragma unroll
    for (int r = 0; r < 16; r++) {
        u64 p = shfl64(v[r], 1 << Q);
        v[r] = fma2(ts, p, v[r]);
    }
}

template <int Q, int CMASK>
__device__ __forceinline__ void cnot_ry(u64* v, u64 ts) {
#pragma unroll
    for (int r = 0; r < 16; r++) {
        u64 old = v[r];
        u64 p = shfl64(old, 1 << Q);
        if (r & CMASK) v[r] = fma2(ts, old, p);
        else           v[r] = fma2(ts, p, old);
    }
}

// Fused CNOT(7->8)+RY(w8) with opposite slot parity across mask-1 shuffle.
__device__ __forceinline__ void cnot_ry0_cross(u64* v, u64 ts) {
#pragma unroll
    for (int r = 0; r < 16; r++) {
        u64 old = v[r];
        float lo, hi; upk2(old, lo, hi);
        float xl = __shfl_xor_sync(0xffffffffu, lo, 1);
        float xh = __shfl_xor_sync(0xffffffffu, hi, 1);
        u64 p = pk2(xh, xl);   // crossed halves
        if (r & 1) v[r] = fma2(ts, old, p);
        else       v[r] = fma2(ts, p, old);
    }
}

// RY on pack bit PM; tn derived from tp by sign flip (ALU, no extra LDS)
template <int PM>
__device__ __forceinline__ void ry_pack(u64* v, u64 tp) {
    const u64 tn = neg2(tp);
#pragma unroll
    for (int r = 0; r < 16; r++) {
        if (!(r & PM)) {
            const int r1 = r | PM;
            u64 X = v[r], Y = v[r1];
            v[r]  = fma2(tn, Y, X);
            v[r1] = fma2(tp, X, Y);
        }
    }
}

__device__ __forceinline__ void ry_slot(u64* v, float t) {
#pragma unroll
    for (int r = 0; r < 16; r++) {
        float lo, hi; upk2(v[r], lo, hi);
        float nlo = fmaf(-t, hi, lo);
        float nhi = fmaf(t, lo, hi);
        v[r] = pk2(nlo, nhi);
    }
}

template <int QC, int PM>
__device__ __forceinline__ void cnot_lp(u64* v, int lane) {
    const bool ct = (lane >> QC) & 1;
#pragma unroll
    for (int r = 0; r < 16; r++) {
        if (!(r & PM)) {
            const int r1 = r | PM;
            u64 a = v[r], b = v[r1];
            v[r]  = ct ? b : a;
            v[r1] = ct ? a : b;
        }
    }
}

__global__ __launch_bounds__(THREADS, 4)
void qnet_kernel(const float* __restrict__ x,      // [B,512]
                 const float* __restrict__ Wred,   // [10,512]
                 const float* __restrict__ bred,   // [10]
                 const float* __restrict__ qp,     // [150]
                 const float* __restrict__ Wpost,  // [2,10]
                 const float* __restrict__ bpost,  // [2]
                 float* __restrict__ out,          // [B,2]
                 int B) {
    __shared__ u64 sW2[5 * 512];          // packed (Wred[2q], Wred[2q+1])
    __shared__ u64 stab[120];             // [0..59]=(t,t), [60..119]=(-t,-t)
    __shared__ float st1[60];             // scalar t per fixed RY
    __shared__ float scc[60];             // cosines for F product
    __shared__ float sbred[10], sWp[20], sbp[2], sF[1];
    __shared__ float spart[WARPS_PER_BLOCK][2][10];  // [elem][K-half][angle]

    const int tid = threadIdx.x;
    for (int i = tid; i < 5 * 512; i += THREADS) {
        int q = i >> 9, col = i & 511;
        sW2[i] = pk2(Wred[(2 * q) * 512 + col], Wred[(2 * q + 1) * 512 + col]);
    }
    if (tid < 60) {
        int k = tid / 10, w = tid % 10;
        float s, c;
        sincosf(qp[(k + 1) * 10 + w] * 0.5f, &s, &c);
        float t = s / c;
        stab[tid] = pk2(t, t); stab[tid + 60] = pk2(-t, -t);
        st1[tid] = t; scc[tid] = c;
    }
    if (tid >= 64 && tid < 74)   sbred[tid - 64] = bred[tid - 64];
    if (tid >= 96 && tid < 116)  sWp[tid - 96] = Wpost[tid - 96];
    if (tid >= 128 && tid < 130) sbp[tid - 128] = bpost[tid - 128];
    __syncthreads();
    if (tid == 0) {
        float f = 1.0f;
#pragma unroll
        for (int i = 0; i < 60; i++) f *= scc[i];
        sF[0] = f;
    }

    const int lane = tid & 31;
    const int warp = tid >> 5;
    const int bbase = blockIdx.x * WARPS_PER_BLOCK;

    // ---- FRONT: split-K, all 8 warps. warp w -> elements (2p, 2p+1),
    //      K columns [h*256, h*256+256), p = w>>1, h = w&1 ----
    {
        const int p = warp >> 1, h = warp & 1;
        const int ea = 2 * p, eb = 2 * p + 1;
        int ba = bbase + ea; if (ba >= B) ba = B - 1;
        int bb = bbase + eb; if (bb >= B) bb = B - 1;
        const float* xra = x + (size_t)ba * 512 + h * 256;
        const float* xrb = x + (size_t)bb * 512 + h * 256;
        const u64* wsec = sW2 + h * 256;
        u64 acca[5], accb[5];
#pragma unroll
        for (int q = 0; q < 5; q++) { acca[q] = 0ull; accb[q] = 0ull; }
#pragma unroll
        for (int j = 0; j < 8; j++) {
            float xva = xra[lane + 32 * j];
            float xvb = xrb[lane + 32 * j];
            u64 xa2 = pk2(xva, xva), xb2 = pk2(xvb, xvb);
#pragma unroll
            for (int q = 0; q < 5; q++) {
                u64 w = wsec[q * 512 + lane + 32 * j];
                acca[q] = fma2(xa2, w, acca[q]);
                accb[q] = fma2(xb2, w, accb[q]);
            }
        }
#pragma unroll
        for (int q = 0; q < 5; q++) {
            u64 ra = wsum2(acca[q]);
            u64 rb = wsum2(accb[q]);
            if (lane == 0) {
                float p0, p1;
                upk2(ra, p0, p1);
                spart[ea][h][2 * q] = p0;
                spart[ea][h][2 * q + 1] = p1;
                upk2(rb, p0, p1);
                spart[eb][h][2 * q] = p0;
                spart[eb][h][2 * q + 1] = p1;
            }
        }
    }
    __syncthreads();

    const int b = bbase + warp;
    if (b >= B) return;

    // ---- combine K-halves + bias + tanh -> this warp's 10 angles ----
    float th[10];
#pragma unroll
    for (int i = 0; i < 10; i++) {
        float pre = spart[warp][0][i] + spart[warp][1][i] + sbred[i];
        th[i] = tanh_apx(pre) * 1.5707963267948966f;
    }

    // ---- product state: H-layer + data RY layer (exact), scaled by F ----
    float gl[5][2], gp[4][2], g9[2];
#pragma unroll
    for (int q = 0; q < 5; q++) {
        float s, c; __sincosf(th[2 * q] * 0.5f, &s, &c);
        gl[q][0] = (c - s) * 0.7071067811865476f;
        gl[q][1] = (c + s) * 0.7071067811865476f;
    }
#pragma unroll
    for (int q = 0; q < 4; q++) {
        float s, c; __sincosf(th[2 * q + 1] * 0.5f, &s, &c);
        gp[q][0] = (c - s) * 0.7071067811865476f;
        gp[q][1] = (c + s) * 0.7071067811865476f;
    }
    {
        float s, c; __sincosf(th[9] * 0.5f, &s, &c);
        g9[0] = (c - s) * 0.7071067811865476f;
        g9[1] = (c + s) * 0.7071067811865476f;
    }
    float F = sF[0] * ((lane & 16) ? gl[0][1] : gl[0][0]);
    F *= ((lane & 8) ? gl[1][1] : gl[1][0]);
    F *= ((lane & 4) ? gl[2][1] : gl[2][0]);
    F *= ((lane & 2) ? gl[3][1] : gl[3][0]);
    F *= ((lane & 1) ? gl[4][1] : gl[4][0]);
    float hiP[4], loP[4];
#pragma unroll
    for (int i = 0; i < 4; i++) {
        hiP[i] = gp[0][(i >> 1) & 1] * gp[1][i & 1];   // wires 1,3
        loP[i] = gp[2][(i >> 1) & 1] * gp[3][i & 1];   // wires 5,7
    }
    u64 G9F = pk2(F * g9[0], F * g9[1]);
    u64 v[16];
#pragma unroll
    for (int r = 0; r < 16; r++) {
        float m = hiP[r >> 2] * loP[r & 3];
        v[r] = mul2(pk2(m, m), G9F);
    }

    // per-lane +-t table offsets (0 -> +t bank, 60 -> -t bank)
    const int o0 = (lane & 16) ? 0 : 60;   // RY w0  (L4)
    const int o2 = (lane & 8)  ? 0 : 60;   // RY w2  (L3)
    const int o4 = (lane & 4)  ? 0 : 60;   // RY w4  (L2)
    const int o6 = (lane & 2)  ? 0 : 60;   // RY w6  (L1)
    const int o8 = (lane & 1)  ? 0 : 60;   // RY w8  (L0)
    const bool L0 = lane & 1;

    // ---- 6 entangling layers, fully unrolled; slot CNOT (8->9) deferred ----
#pragma unroll
    for (int k = 0; k < 6; k++) {
        const u64* T = stab + k * 10;
        cnot_lp<4, 8>(v, lane);   // (0->1)
        cnot_lp<3, 4>(v, lane);   // (2->3)
        cnot_lp<2, 2>(v, lane);   // (4->5)
        cnot_lp<1, 1>(v, lane);   // (6->7)
        cnot_ry<3, 8>(v, T[2 + o2]);   // (1->2)+RY w2
        cnot_ry<2, 4>(v, T[4 + o4]);   // (3->4)+RY w4
        cnot_ry<1, 2>(v, T[6 + o6]);   // (5->6)+RY w6
        if (k & 1) {
            cnot_ry<0, 1>(v, T[8 + o8]);      // (7->8)+RY w8, s uniform
        } else {
            cnot_ry0_cross(v, T[8 + o8]);     // opposite s: cross halves
        }
        ry_lane<4>(v, T[0 + o0]);      // RY w0
        ry_pack<8>(v, T[1]);
        ry_pack<4>(v, T[3]);
        ry_pack<2>(v, T[5]);
        ry_pack<1>(v, T[7]);
        {
            float t = st1[k * 10 + 9];
            float te = ((k & 1) == 0 && L0) ? -t : t;
            ry_slot(v, te);            // RY w9
        }
    }

    // ---- <Z_w> + output projection, fused ----
    const u64 P1 = pk2(1.0f, 1.0f), M1 = pk2(-1.0f, -1.0f);
    u64 S2 = 0ull, A8 = 0ull, A4 = 0ull, A2 = 0ull, A1 = 0ull;
#pragma unroll
    for (int r = 0; r < 16; r++) {
        u64 sq = mul2(v[r], v[r]);
        S2 = add2(S2, sq);
        A8 = fma2((r & 8) ? M1 : P1, sq, A8);
        A4 = fma2((r & 4) ? M1 : P1, sq, A4);
        A2 = fma2((r & 2) ? M1 : P1, sq, A2);
        A1 = fma2((r & 1) ? M1 : P1, sq, A1);
    }
    float sl, sh; upk2(S2, sl, sh);
    float Sv = sl + sh;
    float t9 = sl - sh;
    float l8, h8; upk2(A8, l8, h8); float t1 = l8 + h8;
    float l4, h4; upk2(A4, l4, h4); float t3 = l4 + h4;
    float l2, h2; upk2(A2, l2, h2); float t5 = l2 + h2;
    float l1, h1; upk2(A1, l1, h1); float t7 = l1 + h1;
    float t0 = (lane & 16) ? -Sv : Sv;
    float t2 = (lane & 8)  ? -Sv : Sv;
    float t4 = (lane & 4)  ? -Sv : Sv;
    float t6 = (lane & 2)  ? -Sv : Sv;
    float t8 = L0 ? -Sv : Sv;

    float y0 = sWp[0] * t0 + sWp[1] * t1 + sWp[2] * t2 + sWp[3] * t3 + sWp[4] * t4
             + sWp[5] * t5 + sWp[6] * t6 + sWp[7] * t7 + sWp[8] * t8 + sWp[9] * t9;
    float y1 = sWp[10] * t0 + sWp[11] * t1 + sWp[12] * t2 + sWp[13] * t3 + sWp[14] * t4
             + sWp[15] * t5 + sWp[16] * t6 + sWp[17] * t7 + sWp[18] * t8 + sWp[19] * t9;
    u64 y2 = wsum2(pk2(y0, y1));
    if (lane == 0) {
        float r0, r1; upk2(y2, r0, r1);
        out[2 * (size_t)b + 0] = r0 + sbp[0];
        out[2 * (size_t)b + 1] = r1 + sbp[1];
    }
}

extern "C" void kernel_launch(void* const* d_in, const int* in_sizes, int n_in,
                              void* d_out, int out_size) {
    const float* x     = (const float*)d_in[0];
    const float* Wred  = (const float*)d_in[1];
    const float* bred  = (const float*)d_in[2];
    const float* qp    = (const float*)d_in[3];
    const float* Wpost = (const float*)d_in[4];
    const float* bpost = (const float*)d_in[5];
    float* out = (float*)d_out;

    int B = in_sizes[0] / 512;
    int blocks = (B + WARPS_PER_BLOCK - 1) / WARPS_PER_BLOCK;
    qnet_kernel<<<blocks, THREADS>>>(x, Wred, bred, qp, Wpost, bpost, out, B);
}